// round 4
// baseline (speedup 1.0000x reference)
#include <cuda_runtime.h>
#include <cuda_bf16.h>

#define N_VOX 400000
#define CCH   32
#define KK    27
#define SMEM_BYTES (KK * CCH * CCH * 4)   // 110592 B

// scratch for intermediate features h1 (51.2 MB, static device global — no alloc)
__device__ float g_h[(size_t)N_VOX * CCH];

// One warp per voxel (lane = output channel). W tile (27*32*32 f32) staged in SMEM.
// FINAL=false: out = relu(LN(conv(x)))
// FINAL=true : out = relu(LN(conv(x)) + resid)
template <bool FINAL>
__global__ void __launch_bounds__(1024, 1)
conv_ln_kernel(const float* __restrict__ feats,
               const float* __restrict__ resid,
               const int*   __restrict__ nbr,
               const float* __restrict__ W,
               const float* __restrict__ gamma,
               const float* __restrict__ beta,
               float* __restrict__ out)
{
    extern __shared__ float Ws[];
    for (int t = threadIdx.x; t < KK * CCH * CCH; t += blockDim.x)
        Ws[t] = W[t];
    __syncthreads();

    const int lane   = threadIdx.x & 31;
    const int warp   = (blockIdx.x * blockDim.x + threadIdx.x) >> 5;
    const int nwarps = (gridDim.x * blockDim.x) >> 5;

    const float gl = gamma[lane];
    const float bl = beta[lane];

    for (int i = warp; i < N_VOX; i += nwarps) {
        // lanes 0..26 each fetch one neighbor index for this voxel
        int my_idx = (lane < KK) ? nbr[lane * N_VOX + i] : -1;

        float acc = 0.0f;
        #pragma unroll 1
        for (int k = 0; k < KK; k++) {
            int idx = __shfl_sync(0xffffffffu, my_idx, k);
            if (idx >= 0) {                       // warp-uniform branch
                float g = feats[idx * CCH + lane];   // coalesced 128B gather
                const float* Wk = Ws + k * (CCH * CCH);
                #pragma unroll
                for (int cin = 0; cin < CCH; cin++) {
                    float gv = __shfl_sync(0xffffffffu, g, cin);
                    acc = fmaf(gv, Wk[cin * CCH + lane], acc);
                }
            }
        }

        // LayerNorm over the 32 channels (one warp)
        float s = acc;
        #pragma unroll
        for (int o = 16; o; o >>= 1) s += __shfl_xor_sync(0xffffffffu, s, o);
        float mu = s * (1.0f / 32.0f);
        float d  = acc - mu;
        float v  = d * d;
        #pragma unroll
        for (int o = 16; o; o >>= 1) v += __shfl_xor_sync(0xffffffffu, v, o);
        v *= (1.0f / 32.0f);

        float h = d * rsqrtf(v + 1e-6f) * gl + bl;
        if (FINAL) h += resid[i * CCH + lane];
        out[i * CCH + lane] = fmaxf(h, 0.0f);
    }
}

extern "C" void kernel_launch(void* const* d_in, const int* in_sizes, int n_in,
                              void* d_out, int out_size)
{
    const float* x   = (const float*)d_in[0];
    const int*   nbr = (const int*)  d_in[1];
    const float* W1  = (const float*)d_in[2];
    const float* g1  = (const float*)d_in[3];
    const float* b1  = (const float*)d_in[4];
    const float* W2  = (const float*)d_in[5];
    const float* g2  = (const float*)d_in[6];
    const float* b2  = (const float*)d_in[7];
    float* out = (float*)d_out;

    void* hptr = nullptr;
    cudaGetSymbolAddress(&hptr, g_h);
    float* h = (float*)hptr;

    cudaFuncSetAttribute(conv_ln_kernel<false>,
                         cudaFuncAttributeMaxDynamicSharedMemorySize, SMEM_BYTES);
    cudaFuncSetAttribute(conv_ln_kernel<true>,
                         cudaFuncAttributeMaxDynamicSharedMemorySize, SMEM_BYTES);

    const int threads = 1024;
    const int blocks  = 296;   // persistent-ish grid-stride; ~43 voxels per warp

    conv_ln_kernel<false><<<blocks, threads, SMEM_BYTES>>>(x, nullptr, nbr, W1, g1, b1, h);
    conv_ln_kernel<true ><<<blocks, threads, SMEM_BYTES>>>(h, x,       nbr, W2, g2, b2, out);
}